// round 3
// baseline (speedup 1.0000x reference)
#include <cuda_runtime.h>
#include <math.h>

// N=200000, H=8, D=64  => rows = N*H = 1,600,000 ; float4s = 25,600,000
// Block: 128 rows = 2048 float4. 256 threads x 8 float4 each (strided by 256
// for perfect coalescing). Grid = 12,500 blocks.

#define ROWS_PER_BLOCK 128
#define THREADS 256
#define V4_PER_BLOCK (ROWS_PER_BLOCK * 16)   // 2048
#define SEGS 8

__global__ __launch_bounds__(THREADS)
void emma_merge_kernel(const float4* __restrict__ x,
                       const float* __restrict__ max_a,
                       const float4* __restrict__ his_x,
                       const float* __restrict__ his_m,
                       const float* __restrict__ agg_n,
                       const float* __restrict__ inv_w,
                       float4* __restrict__ out)
{
    __shared__ float p_s[ROWS_PER_BLOCK];
    __shared__ float q_s[ROWS_PER_BLOCK];

    const int b = blockIdx.x;
    const int t = threadIdx.x;

    // Threads 0..127 each compute one row's scalars (2 expf per row).
    if (t < ROWS_PER_BLOCK) {
        const int row = b * ROWS_PER_BLOCK + t;   // row in [0, N*H)
        const int n   = row >> 3;                 // H = 8
        const float iw   = __ldg(inv_w);
        const float beta = fminf(fmaxf(1.0f - iw * __ldg(&agg_n[n]), 0.0f), 1.0f);
        const float ma   = __ldg(&max_a[row]);
        const float hm   = __ldg(&his_m[row]);
        const float mm   = fmaxf(ma, hm);

        float dp = hm - mm;
        float dq = ma - mm;
        if (isnan(dp)) dp = -INFINITY;            // nan_to_num(..., nan=-inf)
        if (isnan(dq)) dq = -INFINITY;

        float p = expf(dp) * beta;
        float q = expf(dq);
        const float tt  = fmaxf(p + q, 1.0f);     // clamp_min_(1.0)
        const float inv = 1.0f / tt;
        p_s[t] = p * inv;
        q_s[t] = q * inv;
    }
    __syncthreads();

    const long long base = (long long)b * V4_PER_BLOCK;

    // Front-batch all 16 loads (8 x + 8 his_x), evict-first (streaming).
    float4 xv[SEGS], hv[SEGS];
#pragma unroll
    for (int k = 0; k < SEGS; k++)
        xv[k] = __ldcs(&x[base + t + k * THREADS]);
#pragma unroll
    for (int k = 0; k < SEGS; k++)
        hv[k] = __ldcs(&his_x[base + t + k * THREADS]);

#pragma unroll
    for (int k = 0; k < SEGS; k++) {
        const int rl = (t + k * THREADS) >> 4;    // local row 0..127 (warp-broadcast)
        const float p = p_s[rl];
        const float q = q_s[rl];
        float4 o;
        o.x = fmaf(hv[k].x, p, xv[k].x * q);
        o.y = fmaf(hv[k].y, p, xv[k].y * q);
        o.z = fmaf(hv[k].z, p, xv[k].z * q);
        o.w = fmaf(hv[k].w, p, xv[k].w * q);
        // Streaming (evict-first) store: out is write-once.
        const float4* ptr = &out[base + t + k * THREADS];
        asm volatile("st.global.cs.v4.f32 [%0], {%1, %2, %3, %4};"
                     :: "l"(ptr), "f"(o.x), "f"(o.y), "f"(o.z), "f"(o.w)
                     : "memory");
    }
}

extern "C" void kernel_launch(void* const* d_in, const int* in_sizes, int n_in,
                              void* d_out, int out_size)
{
    const float4* x     = (const float4*)d_in[0];
    const float*  max_a = (const float*) d_in[1];
    const float4* his_x = (const float4*)d_in[2];
    const float*  his_m = (const float*) d_in[3];
    const float*  agg_n = (const float*) d_in[4];
    const float*  inv_w = (const float*) d_in[5];
    float4*       out   = (float4*)      d_out;

    const int rows   = in_sizes[1];               // 1,600,000
    const int blocks = rows / ROWS_PER_BLOCK;     // 12,500

    emma_merge_kernel<<<blocks, THREADS>>>(x, max_a, his_x, his_m, agg_n, inv_w, out);
}